// round 15
// baseline (speedup 1.0000x reference)
#include <cuda_runtime.h>

#define N_OUT   100000
#define KBINS   9
#define C_IN    32
#define C_A     24
#define C_B     8
#define C_OUT   32
#define JTOT    (KBINS * C_IN)      // 288
#define GROUPS  (N_OUT / 8)         // 12500
#define E_MAX   1600000

// T layout: [branch][o][R] floats.
#define R       288
#define BOFF    2312                // 8*288 + 8
// PS: [o][pairteam 16][32 feats], 128B rows.
#define NPT     16

typedef unsigned long long ull;

__device__ __forceinline__ ull pack2(float x, float y) {
    ull r; asm("mov.b64 %0, {%1, %2};" : "=l"(r) : "f"(x), "f"(y)); return r;
}
__device__ __forceinline__ void unpack2(ull v, float &x, float &y) {
    asm("mov.b64 {%0, %1}, %2;" : "=f"(x), "=f"(y) : "l"(v));
}
__device__ __forceinline__ ull add2(ull a, ull b) {
    ull r; asm("add.rn.f32x2 %0, %1, %2;" : "=l"(r) : "l"(a), "l"(b)); return r;
}
__device__ __forceinline__ ull fma2(ull a, ull b, ull c) {
    ull r; asm("fma.rn.f32x2 %0, %1, %2, %3;" : "=l"(r) : "l"(a), "l"(b), "l"(c)); return r;
}

// ---- device scratch --------------------------------------------------------
__device__ float g_Wt[JTOT][C_OUT];       // Wt[j][f], j = k*32+c
__device__ int   g_row_start[N_OUT + 1];
__device__ float g_imp[N_OUT];            // per-output importance sum
__device__ __align__(16) int2 g_edge[E_MAX];  // sorted by (out, bin)

// ---------------------------------------------------------------------------
// Prep: weight transpose + CSR row starts via boundary scatter.
__global__ void prep_misc_kernel(const float* __restrict__ W_a,
                                 const float* __restrict__ W_b,
                                 const int* __restrict__ out_idx, int E) {
    int idx = blockIdx.x * blockDim.x + threadIdx.x;
    if (idx < JTOT * C_OUT) {
        int j = idx / C_OUT, f = idx % C_OUT;
        int k = j / C_IN,  c = j % C_IN;
        float w = (f < C_A) ? W_a[(k * C_IN + c) * C_A + f]
                            : W_b[(k * C_IN + c) * C_B + (f - C_A)];
        g_Wt[j][f] = w;
    }
    if (idx < E) {
        const int cur  = out_idx[idx];
        const int prev = (idx == 0) ? -1 : out_idx[idx - 1];
        for (int n = prev + 1; n <= cur; n++)      // boundary: rare, short
            g_row_start[n] = idx;
        if (idx == E - 1)
            for (int n = cur + 1; n <= N_OUT; n++)
                g_row_start[n] = E;
    }
}

// Warp-per-output counting sort by bin + per-output importance sum.
__global__ void sort_edges_kernel(const int* __restrict__ nb_idx,
                                  const int* __restrict__ nb_k,
                                  const float* __restrict__ importance) {
    const int wid  = (blockIdx.x * blockDim.x + threadIdx.x) >> 5;
    const int lane = threadIdx.x & 31;
    if (wid >= N_OUT) return;
    const int e0 = g_row_start[wid], e1 = g_row_start[wid + 1];
    if (e0 == e1) {
        if (lane == 0) g_imp[wid] = 0.f;
        return;
    }
    const unsigned lt = (1u << lane) - 1u;

    int h[KBINS];
    #pragma unroll
    for (int q = 0; q < KBINS; q++) h[q] = 0;
    for (int base = e0; base < e1; base += 32) {
        const int e = base + lane;
        const int k = (e < e1) ? nb_k[e] : -1;
        #pragma unroll
        for (int q = 0; q < KBINS; q++)
            h[q] += __popc(__ballot_sync(0xffffffffu, k == q));
    }
    int off[KBINS];
    off[0] = 0;
    #pragma unroll
    for (int q = 1; q < KBINS; q++) off[q] = off[q - 1] + h[q - 1];

    float isum = 0.f;
    for (int base = e0; base < e1; base += 32) {
        const int e = base + lane;
        const bool valid = e < e1;
        const int k = valid ? nb_k[e] : -1;
        unsigned bal[KBINS];
        #pragma unroll
        for (int q = 0; q < KBINS; q++)
            bal[q] = __ballot_sync(0xffffffffu, k == q);
        int pos = 0;
        #pragma unroll
        for (int q = 0; q < KBINS; q++)
            if (k == q) pos = off[q] + __popc(bal[q] & lt);
        if (valid) {
            const int ni = nb_idx[e];
            const float ii = importance[ni];
            isum += ii;
            g_edge[e0 + pos] = make_int2((ni * C_IN) | (k << 23),
                                         __float_as_int(ii));
        }
        #pragma unroll
        for (int q = 0; q < KBINS; q++) off[q] += __popc(bal[q]);
    }
    #pragma unroll
    for (int d = 16; d > 0; d >>= 1)
        isum += __shfl_xor_sync(0xffffffffu, isum, d);
    if (lane == 0) g_imp[wid] = isum;
}

// ---------------------------------------------------------------------------
// Main fused kernel. 256 threads = 8 warps; group = 8 outputs; TARGET 5 CTA/SM.
// Phase 1: warp-per-output, sorted-bin running flush (R11).
// Phase 2: 32 teams x 8 lanes; lane owns features 4q..4q+3 (LDS.32 + 2 FMA2
//   per j); xor-16 shfl merges team pairs -> PS[16]; W reloaded per group.
// ---------------------------------------------------------------------------
__global__ __launch_bounds__(256, 5)
void sparse_conv_main(const float* __restrict__ feats,
                      const float* __restrict__ b_a,
                      const float* __restrict__ b_b,
                      float*       __restrict__ out) {
    __shared__ float T[2 * BOFF];              // 18.5KB
    __shared__ float PS[8 * NPT * C_OUT];      // 16KB
    // total 34.5KB -> 5 CTAs/SM fits (172KB)

    const int tid  = threadIdx.x;
    const int w    = tid >> 5;          // phase-1 output, reduce output
    const int lane = tid & 31;          // phase-1 channel, reduce feature
    const int team = tid >> 3;          // phase-2 team (0..31): 9-j slice
    const int q    = tid & 7;           // phase-2 lane: features 4q..4q+3

    const float bias = (lane < C_A) ? b_a[lane] : b_b[lane - C_A];

    const float* Tlane = T + ((q < 6) ? 0 : BOFF) + (team & 31) * 9;
    const float* Wsrc  = &g_Wt[(team & 31) * 9][4 * q];   // row stride 32 floats

    float* const t0 = T + w * R + lane;
    float* const t1 = t0 + BOFF;

    // PS pair-team id for this thread's store (valid when lane < 16).
    const int pt = 2 * w + ((lane >> 3) & 1);

#define UPDATE(EX, EY, V) do {                                    \
        const int nb_ = ((unsigned)(EX)) >> 23;                   \
        if (nb_ != cur) {                                         \
            float sa_, sb_; unpack2(run, sa_, sb_);               \
            t0[cur * 32] = sa_;                                   \
            t1[cur * 32] = sb_;                                   \
            touched |= (1u << cur); run = 0ull; cur = nb_;        \
        }                                                         \
        const float ii_ = __int_as_float(EY);                     \
        run = add2(run, pack2((V), (V) * ii_));                   \
    } while (0)

    for (int g = blockIdx.x; g < GROUPS; g += gridDim.x) {
        // =================== Phase 1 ===================
        const int n  = g * 8 + w;
        const int e0 = g_row_start[n];
        const int e1 = g_row_start[n + 1];

        ull run = 0ull; int cur = 0; unsigned touched = 0u;

        int e = e0;
        if ((e & 1) && e < e1) {            // align to even index for int4
            const int2 A = g_edge[e];
            const float v = __ldg(&feats[(A.x & 0x7FFFFF) + lane]);
            UPDATE(A.x, A.y, v);
            ++e;
        }
        for (; e + 4 <= e1; e += 4) {
            const int4 P = *(const int4*)&g_edge[e];
            const int4 Q = *(const int4*)&g_edge[e + 2];
            const float v0 = __ldg(&feats[(P.x & 0x7FFFFF) + lane]);
            const float v1 = __ldg(&feats[(P.z & 0x7FFFFF) + lane]);
            const float v2 = __ldg(&feats[(Q.x & 0x7FFFFF) + lane]);
            const float v3 = __ldg(&feats[(Q.z & 0x7FFFFF) + lane]);
            UPDATE(P.x, P.y, v0); UPDATE(P.z, P.w, v1);
            UPDATE(Q.x, Q.y, v2); UPDATE(Q.z, Q.w, v3);
        }
        if (e + 2 <= e1) {
            const int4 P = *(const int4*)&g_edge[e];
            const float v0 = __ldg(&feats[(P.x & 0x7FFFFF) + lane]);
            const float v1 = __ldg(&feats[(P.z & 0x7FFFFF) + lane]);
            UPDATE(P.x, P.y, v0); UPDATE(P.z, P.w, v1);
            e += 2;
        }
        if (e < e1) {
            const int2 A = g_edge[e];
            const float v = __ldg(&feats[(A.x & 0x7FFFFF) + lane]);
            UPDATE(A.x, A.y, v);
        }
        if (e1 > e0) {
            float sa, sb; unpack2(run, sa, sb);
            t0[cur * 32] = sa;
            t1[cur * 32] = sb;
            touched |= (1u << cur);
        }
        #pragma unroll
        for (int qq = 0; qq < KBINS; qq++)
            if (!((touched >> qq) & 1u)) {
                t0[qq * 32] = 0.f;
                t1[qq * 32] = 0.f;
            }
        __syncthreads();   // barrier A

        // =================== Phase 2: F=4 team GEMM ===================
        // Reload W each group (volatile keeps the 36 regs phase-2-only).
        ull W01[9], W23[9];
        #pragma unroll
        for (int jj = 0; jj < 9; jj++) {
            float w0, w1, w2, w3;
            asm volatile("ld.global.nc.v4.f32 {%0, %1, %2, %3}, [%4];"
                         : "=f"(w0), "=f"(w1), "=f"(w2), "=f"(w3)
                         : "l"(Wsrc + jj * C_OUT));
            W01[jj] = pack2(w0, w1);
            W23[jj] = pack2(w2, w3);
        }
        #pragma unroll
        for (int o = 0; o < 8; o++) {
            const float* sp = Tlane + o * R;
            ull a01 = 0ull, a23 = 0ull;
            #pragma unroll
            for (int jj = 0; jj < 9; jj++) {           // 9 LDS.32 (broadcast)
                const float s = sp[jj];
                const ull s2 = pack2(s, s);
                a01 = fma2(s2, W01[jj], a01);
                a23 = fma2(s2, W23[jj], a23);
            }
            // merge team pairs (xor-16: teams 4w+{0,2} and 4w+{1,3})
            a01 = add2(a01, __shfl_xor_sync(0xffffffffu, a01, 16));
            a23 = add2(a23, __shfl_xor_sync(0xffffffffu, a23, 16));
            if (lane < 16) {
                float x0, x1, x2, x3;
                unpack2(a01, x0, x1);
                unpack2(a23, x2, x3);
                *(float4*)&PS[(o * NPT + pt) * C_OUT + 4 * q] =
                    make_float4(x0, x1, x2, x3);
            }
        }
        __syncthreads();   // barrier B

        // =================== Reduce + epilogue: warp w -> output w ==========
        {
            const int n2 = g * 8 + w;
            const float* pr = PS + (w * NPT) * C_OUT + lane;
            float s0 = pr[0 * C_OUT] + pr[1 * C_OUT];
            float s1 = pr[2 * C_OUT] + pr[3 * C_OUT];
            float s2 = pr[4 * C_OUT] + pr[5 * C_OUT];
            float s3 = pr[6 * C_OUT] + pr[7 * C_OUT];
            float s4 = pr[8 * C_OUT] + pr[9 * C_OUT];
            float s5 = pr[10 * C_OUT] + pr[11 * C_OUT];
            float s6 = pr[12 * C_OUT] + pr[13 * C_OUT];
            float s7 = pr[14 * C_OUT] + pr[15 * C_OUT];
            float s = ((s0 + s1) + (s2 + s3)) + ((s4 + s5) + (s6 + s7));
            const float iv    = __ldg(&g_imp[n2]);         // broadcast
            const float denom = (iv > 0.f) ? iv : 1.f;
            float r = (lane < C_A) ? (s + bias) : (s / denom + bias);
            out[n2 * C_OUT + lane] = fmaxf(r, 0.f);
            if (lane == 0) out[N_OUT * C_OUT + n2] = iv;
        }
    }
#undef UPDATE
}

// ---------------------------------------------------------------------------
extern "C" void kernel_launch(void* const* d_in, const int* in_sizes, int n_in,
                              void* d_out, int out_size) {
    const float* feats      = (const float*)d_in[0];
    const float* importance = (const float*)d_in[1];
    const float* W_a        = (const float*)d_in[2];
    const float* b_a        = (const float*)d_in[3];
    const float* W_b        = (const float*)d_in[4];
    const float* b_b        = (const float*)d_in[5];
    const int*   nb_idx     = (const int*)d_in[6];
    const int*   nb_k       = (const int*)d_in[7];
    const int*   nb_out     = (const int*)d_in[8];
    const int E = in_sizes[6];

    prep_misc_kernel<<<(E + 255) / 256, 256>>>(W_a, W_b, nb_out, E);
    sort_edges_kernel<<<(N_OUT * 32 + 255) / 256, 256>>>(nb_idx, nb_k, importance);
    sparse_conv_main<<<740, 256>>>(feats, b_a, b_b, (float*)d_out);
}

// round 16
// speedup vs baseline: 1.3122x; 1.3122x over previous
#include <cuda_runtime.h>

#define N_OUT   100000
#define KBINS   9
#define C_IN    32
#define C_A     24
#define C_B     8
#define C_OUT   32
#define JTOT    (KBINS * C_IN)      // 288
#define GROUPS  (N_OUT / 8)         // 12500
#define E_MAX   1600000

// Phase-2 team geometry: 16 teams x 16 lanes; slice = 18 j per team.
#define TSLICE  18
#define NTEAMS  16
// T layout: [branch][o][R] floats, branch offset BOFF.
#define R       292                 // even, R%32=4
#define BOFF    2344                // 8*292 + 8 ; BOFF%32 = 8
#define PSTR    34                  // even: 8B-aligned float2 partial stores

typedef unsigned long long ull;

__device__ __forceinline__ ull pack2(float x, float y) {
    ull r; asm("mov.b64 %0, {%1, %2};" : "=l"(r) : "f"(x), "f"(y)); return r;
}
__device__ __forceinline__ void unpack2(ull v, float &x, float &y) {
    asm("mov.b64 {%0, %1}, %2;" : "=f"(x), "=f"(y) : "l"(v));
}
__device__ __forceinline__ ull add2(ull a, ull b) {
    ull r; asm("add.rn.f32x2 %0, %1, %2;" : "=l"(r) : "l"(a), "l"(b)); return r;
}

// ---- device scratch --------------------------------------------------------
__device__ float g_Wt[JTOT][C_OUT];       // Wt[j][f], j = k*32+c
__device__ int   g_row_start[N_OUT + 1];
__device__ float g_imp[N_OUT];            // per-output importance sum
__device__ __align__(16) int2 g_edge[E_MAX];  // sorted by (out, bin)

// ---------------------------------------------------------------------------
// Prep: weight transpose + CSR row starts via boundary scatter.
__global__ void prep_misc_kernel(const float* __restrict__ W_a,
                                 const float* __restrict__ W_b,
                                 const int* __restrict__ out_idx, int E) {
    int idx = blockIdx.x * blockDim.x + threadIdx.x;
    if (idx < JTOT * C_OUT) {
        int j = idx / C_OUT, f = idx % C_OUT;
        int k = j / C_IN,  c = j % C_IN;
        float w = (f < C_A) ? W_a[(k * C_IN + c) * C_A + f]
                            : W_b[(k * C_IN + c) * C_B + (f - C_A)];
        g_Wt[j][f] = w;
    }
    if (idx < E) {
        const int cur  = out_idx[idx];
        const int prev = (idx == 0) ? -1 : out_idx[idx - 1];
        for (int n = prev + 1; n <= cur; n++)      // boundary: rare, short
            g_row_start[n] = idx;
        if (idx == E - 1)
            for (int n = cur + 1; n <= N_OUT; n++)
                g_row_start[n] = E;
    }
}

// Warp-per-output counting sort by bin + per-output importance sum.
// Fast path for rows <= 32 edges (the common case): one load, one ballot
// sweep produces histogram + rank + scatter position together.
__global__ void sort_edges_kernel(const int* __restrict__ nb_idx,
                                  const int* __restrict__ nb_k,
                                  const float* __restrict__ importance) {
    const int wid  = (blockIdx.x * blockDim.x + threadIdx.x) >> 5;
    const int lane = threadIdx.x & 31;
    if (wid >= N_OUT) return;
    const int e0 = g_row_start[wid], e1 = g_row_start[wid + 1];
    if (e0 == e1) {
        if (lane == 0) g_imp[wid] = 0.f;
        return;
    }
    const unsigned lt = (1u << lane) - 1u;

    if (e1 - e0 <= 32) {
        // ---- single-batch fast path ----
        const int e = e0 + lane;
        const bool valid = e < e1;
        const int k = valid ? nb_k[e] : -1;
        int pos = 0, pre = 0;
        #pragma unroll
        for (int q = 0; q < KBINS; q++) {
            const unsigned bal = __ballot_sync(0xffffffffu, k == q);
            if (k == q) pos = pre + __popc(bal & lt);
            pre += __popc(bal);
        }
        float isum = 0.f;
        if (valid) {
            const int ni = nb_idx[e];
            const float ii = importance[ni];
            isum = ii;
            g_edge[e0 + pos] = make_int2((ni * C_IN) | (k << 23),
                                         __float_as_int(ii));
        }
        #pragma unroll
        for (int d = 16; d > 0; d >>= 1)
            isum += __shfl_xor_sync(0xffffffffu, isum, d);
        if (lane == 0) g_imp[wid] = isum;
        return;
    }

    // ---- general two-pass path (rows > 32 edges) ----
    int h[KBINS];
    #pragma unroll
    for (int q = 0; q < KBINS; q++) h[q] = 0;
    for (int base = e0; base < e1; base += 32) {
        const int e = base + lane;
        const int k = (e < e1) ? nb_k[e] : -1;
        #pragma unroll
        for (int q = 0; q < KBINS; q++)
            h[q] += __popc(__ballot_sync(0xffffffffu, k == q));
    }
    int off[KBINS];
    off[0] = 0;
    #pragma unroll
    for (int q = 1; q < KBINS; q++) off[q] = off[q - 1] + h[q - 1];

    float isum = 0.f;
    for (int base = e0; base < e1; base += 32) {
        const int e = base + lane;
        const bool valid = e < e1;
        const int k = valid ? nb_k[e] : -1;
        unsigned bal[KBINS];
        #pragma unroll
        for (int q = 0; q < KBINS; q++)
            bal[q] = __ballot_sync(0xffffffffu, k == q);
        int pos = 0;
        #pragma unroll
        for (int q = 0; q < KBINS; q++)
            if (k == q) pos = off[q] + __popc(bal[q] & lt);
        if (valid) {
            const int ni = nb_idx[e];
            const float ii = importance[ni];
            isum += ii;
            g_edge[e0 + pos] = make_int2((ni * C_IN) | (k << 23),
                                         __float_as_int(ii));
        }
        #pragma unroll
        for (int q = 0; q < KBINS; q++) off[q] += __popc(bal[q]);
    }
    #pragma unroll
    for (int d = 16; d > 0; d >>= 1)
        isum += __shfl_xor_sync(0xffffffffu, isum, d);
    if (lane == 0) g_imp[wid] = isum;
}

// ---------------------------------------------------------------------------
// Main fused kernel (R11, verified 164.4us total).
// 256 threads = 8 warps; group = 8 outputs; 4 CTAs/SM.
// Phase 1: warp-per-output, sorted-bin running accumulator -> T rows.
// Phase 2: 16 teams x 16 lanes; lane owns features (2tl,2tl+1); W reloaded
//          per group via volatile asm so its 36 regs are phase-2-only live.
// ---------------------------------------------------------------------------
__global__ __launch_bounds__(256, 4)
void sparse_conv_main(const float* __restrict__ feats,
                      const float* __restrict__ b_a,
                      const float* __restrict__ b_b,
                      float*       __restrict__ out) {
    __shared__ float T[2 * BOFF];             // Ta at 0, Tb at BOFF   (18.8KB)
    __shared__ float PS[8 * NTEAMS * PSTR];   // partials [o][team][34] (17.4KB)

    const int tid  = threadIdx.x;
    const int w    = tid >> 5;          // phase-1 output, reduce output
    const int lane = tid & 31;          // phase-1 channel, reduce feature
    const int team = tid >> 4;          // phase-2 team (0..15): j-slice
    const int tl   = tid & 15;          // phase-2 lane: features (2tl, 2tl+1)

    const float bias = (lane < C_A) ? b_a[lane] : b_b[lane - C_A];

    const float* Tlane = T + ((2 * tl < C_A) ? 0 : BOFF) + team * TSLICE;
    const float* Wsrc  = &g_Wt[team * TSLICE][2 * tl];   // stride 32 floats/row

    float* const t0 = T + w * R + lane;
    float* const t1 = t0 + BOFF;

#define UPDATE(EX, EY, V) do {                                    \
        const int nb_ = ((unsigned)(EX)) >> 23;                   \
        if (nb_ != cur) {                                         \
            float sa_, sb_; unpack2(run, sa_, sb_);               \
            t0[cur * 32] = sa_;                                   \
            t1[cur * 32] = sb_;                                   \
            touched |= (1u << cur); run = 0ull; cur = nb_;        \
        }                                                         \
        const float ii_ = __int_as_float(EY);                     \
        run = add2(run, pack2((V), (V) * ii_));                   \
    } while (0)

    for (int g = blockIdx.x; g < GROUPS; g += gridDim.x) {
        // =================== Phase 1 ===================
        const int n  = g * 8 + w;
        const int e0 = g_row_start[n];
        const int e1 = g_row_start[n + 1];

        ull run = 0ull; int cur = 0; unsigned touched = 0u;

        int e = e0;
        if ((e & 1) && e < e1) {            // align to even index for int4
            const int2 A = g_edge[e];
            const float v = __ldg(&feats[(A.x & 0x7FFFFF) + lane]);
            UPDATE(A.x, A.y, v);
            ++e;
        }
        for (; e + 4 <= e1; e += 4) {
            const int4 P = *(const int4*)&g_edge[e];
            const int4 Q = *(const int4*)&g_edge[e + 2];
            const float v0 = __ldg(&feats[(P.x & 0x7FFFFF) + lane]);
            const float v1 = __ldg(&feats[(P.z & 0x7FFFFF) + lane]);
            const float v2 = __ldg(&feats[(Q.x & 0x7FFFFF) + lane]);
            const float v3 = __ldg(&feats[(Q.z & 0x7FFFFF) + lane]);
            UPDATE(P.x, P.y, v0); UPDATE(P.z, P.w, v1);
            UPDATE(Q.x, Q.y, v2); UPDATE(Q.z, Q.w, v3);
        }
        if (e + 2 <= e1) {
            const int4 P = *(const int4*)&g_edge[e];
            const float v0 = __ldg(&feats[(P.x & 0x7FFFFF) + lane]);
            const float v1 = __ldg(&feats[(P.z & 0x7FFFFF) + lane]);
            UPDATE(P.x, P.y, v0); UPDATE(P.z, P.w, v1);
            e += 2;
        }
        if (e < e1) {
            const int2 A = g_edge[e];
            const float v = __ldg(&feats[(A.x & 0x7FFFFF) + lane]);
            UPDATE(A.x, A.y, v);
        }
        if (e1 > e0) {
            float sa, sb; unpack2(run, sa, sb);
            t0[cur * 32] = sa;
            t1[cur * 32] = sb;
            touched |= (1u << cur);
        }
        #pragma unroll
        for (int q = 0; q < KBINS; q++)
            if (!((touched >> q) & 1u)) {
                t0[q * 32] = 0.f;
                t1[q * 32] = 0.f;
            }
        __syncthreads();   // barrier A

        // =================== Phase 2: team GEMM ===================
        // Reload W each group (volatile: keeps the 36 regs phase-2-only).
        float2 Wp[TSLICE];
        #pragma unroll
        for (int jj = 0; jj < TSLICE; jj++) {
            float wx, wy;
            asm volatile("ld.global.nc.v2.f32 {%0, %1}, [%2];"
                         : "=f"(wx), "=f"(wy)
                         : "l"(Wsrc + jj * C_OUT));
            Wp[jj] = make_float2(wx, wy);
        }
        #pragma unroll
        for (int o = 0; o < 8; o++) {
            const float2* sp = (const float2*)(Tlane + o * R);
            float ax = 0.f, ay = 0.f;
            #pragma unroll
            for (int jp = 0; jp < TSLICE / 2; jp++) {      // 9 LDS.64
                const float2 s = sp[jp];
                ax = fmaf(s.x, Wp[2 * jp].x, ax);
                ay = fmaf(s.x, Wp[2 * jp].y, ay);
                ax = fmaf(s.y, Wp[2 * jp + 1].x, ax);
                ay = fmaf(s.y, Wp[2 * jp + 1].y, ay);
            }
            *(float2*)&PS[(o * NTEAMS + team) * PSTR + 2 * tl] =
                make_float2(ax, ay);
        }
        __syncthreads();   // barrier B

        // =================== Reduce + epilogue: warp w -> output w ==========
        {
            const int n2 = g * 8 + w;
            const float* pr = PS + (w * NTEAMS) * PSTR + lane;
            float s0 = pr[0 * PSTR] + pr[1 * PSTR];
            float s1 = pr[2 * PSTR] + pr[3 * PSTR];
            float s2 = pr[4 * PSTR] + pr[5 * PSTR];
            float s3 = pr[6 * PSTR] + pr[7 * PSTR];
            float s4 = pr[8 * PSTR] + pr[9 * PSTR];
            float s5 = pr[10 * PSTR] + pr[11 * PSTR];
            float s6 = pr[12 * PSTR] + pr[13 * PSTR];
            float s7 = pr[14 * PSTR] + pr[15 * PSTR];
            float s = ((s0 + s1) + (s2 + s3)) + ((s4 + s5) + (s6 + s7));
            const float iv    = __ldg(&g_imp[n2]);         // broadcast
            const float denom = (iv > 0.f) ? iv : 1.f;
            float r = (lane < C_A) ? (s + bias) : (s / denom + bias);
            out[n2 * C_OUT + lane] = fmaxf(r, 0.f);
            if (lane == 0) out[N_OUT * C_OUT + n2] = iv;
        }
    }
#undef UPDATE
}

// ---------------------------------------------------------------------------
extern "C" void kernel_launch(void* const* d_in, const int* in_sizes, int n_in,
                              void* d_out, int out_size) {
    const float* feats      = (const float*)d_in[0];
    const float* importance = (const float*)d_in[1];
    const float* W_a        = (const float*)d_in[2];
    const float* b_a        = (const float*)d_in[3];
    const float* W_b        = (const float*)d_in[4];
    const float* b_b        = (const float*)d_in[5];
    const int*   nb_idx     = (const int*)d_in[6];
    const int*   nb_k       = (const int*)d_in[7];
    const int*   nb_out     = (const int*)d_in[8];
    const int E = in_sizes[6];

    prep_misc_kernel<<<(E + 255) / 256, 256>>>(W_a, W_b, nb_out, E);
    sort_edges_kernel<<<(N_OUT * 32 + 255) / 256, 256>>>(nb_idx, nb_k, importance);
    sparse_conv_main<<<592, 256>>>(feats, b_a, b_b, (float*)d_out);
}